// round 15
// baseline (speedup 1.0000x reference)
#include <cuda_runtime.h>
#include <cuda_fp16.h>
#include <math.h>
#include <stdint.h>

#define NT 16384    // tokens = B*T
#define DD 1024     // hidden
#define FF 4096     // ffn
#define NE 8        // experts
#define NROWS 32768 // 2*NT expert-row slots
#define WGROUPS 2097152  // NE*FF*DD/16 groups per weight tensor

// ---------------- device scratch (static, allocation-free) ----------------
__device__ int    g_count[NE];
__device__ int    g_offset[NE];
__device__ int    g_tokens[NE][NT];
__device__ float  g_gates[NE][NT];
__device__ int    g_slot[NE][NT];
__device__ __half g_X[(size_t)NROWS * DD];      // gathered, fp16, pair-permuted
__device__ __half g_H[(size_t)NROWS * FF];      // gelu(fc), fp16, pair-permuted
__device__ float  g_part[2][(size_t)NT * DD];   // per-slot partial outputs (fp32)
__device__ __half g_Wfc[(size_t)NE * FF * DD];  // fp16 + permuted weights
__device__ __half g_Wpj[(size_t)NE * DD * FF];

// ---------------- helpers ----------------
__device__ __forceinline__ void cp16(uint32_t d, const void* s) {
    asm volatile("cp.async.cg.shared.global [%0], [%1], 16;" :: "r"(d), "l"(s));
}
__device__ __forceinline__ void cp_commit() { asm volatile("cp.async.commit_group;"); }
template<int N> __device__ __forceinline__ void cp_wait() {
    asm volatile("cp.async.wait_group %0;" :: "n"(N));
}
__device__ __forceinline__ uint32_t smem_u32(const void* p) {
    uint32_t a;
    asm("{ .reg .u64 t; cvta.to.shared.u64 t, %1; cvt.u32.u64 %0, t; }" : "=r"(a) : "l"(p));
    return a;
}
// fp16 MMA m16n8k16, fp32 accumulate
__device__ __forceinline__ void mma_f16(float c[4], uint32_t a0, uint32_t a1,
                                        uint32_t a2, uint32_t a3,
                                        uint32_t b0, uint32_t b1) {
    asm volatile(
        "mma.sync.aligned.m16n8k16.row.col.f32.f16.f16.f32 "
        "{%0,%1,%2,%3}, {%4,%5,%6,%7}, {%8,%9}, {%0,%1,%2,%3};"
        : "+f"(c[0]), "+f"(c[1]), "+f"(c[2]), "+f"(c[3])
        : "r"(a0), "r"(a1), "r"(a2), "r"(a3), "r"(b0), "r"(b1));
}
__device__ __forceinline__ float blockReduceSum(float v, float* red) {
    __syncthreads();
    int lane = threadIdx.x & 31, warp = threadIdx.x >> 5;
    #pragma unroll
    for (int o = 16; o; o >>= 1) v += __shfl_xor_sync(0xffffffffu, v, o);
    if (lane == 0) red[warp] = v;
    __syncthreads();
    if (warp == 0) {
        float s = (lane < 8) ? red[lane] : 0.0f;
        #pragma unroll
        for (int o = 4; o; o >>= 1) s += __shfl_xor_sync(0xffffffffu, s, o);
        if (lane == 0) red[0] = s;
    }
    __syncthreads();
    return red[0];
}

// pack 16 floats -> 16 permuted fp16 (pair order [0,4,1,5,2,6,3,7]) as 8 u32
__device__ __forceinline__ void pack16(const float4 f0, const float4 f1,
                                       const float4 f2, const float4 f3,
                                       uint32_t u[8]) {
    __half2 p[8];
    p[0] = __floats2half2_rn(f0.x, f0.y); p[1] = __floats2half2_rn(f0.z, f0.w);
    p[2] = __floats2half2_rn(f1.x, f1.y); p[3] = __floats2half2_rn(f1.z, f1.w);
    p[4] = __floats2half2_rn(f2.x, f2.y); p[5] = __floats2half2_rn(f2.z, f2.w);
    p[6] = __floats2half2_rn(f3.x, f3.y); p[7] = __floats2half2_rn(f3.z, f3.w);
    u[0] = *(uint32_t*)&p[0]; u[1] = *(uint32_t*)&p[4];
    u[2] = *(uint32_t*)&p[1]; u[3] = *(uint32_t*)&p[5];
    u[4] = *(uint32_t*)&p[2]; u[5] = *(uint32_t*)&p[6];
    u[6] = *(uint32_t*)&p[3]; u[7] = *(uint32_t*)&p[7];
}

// ---------------- small kernels ----------------
__global__ void k_zero() { if (threadIdx.x < NE) g_count[threadIdx.x] = 0; }

// grid (NT, 2): y=0 -> router blocks; y=1 -> weight-conversion blocks (both tensors).
__global__ void k_router(const float* __restrict__ x, const float* __restrict__ rw,
                         float* __restrict__ logits_out,
                         const float* __restrict__ wfc, const float* __restrict__ wpj) {
    if (blockIdx.y == 1) {
        // pure conversion block: 16384 blocks x 256 threads covers 2*WGROUPS groups
        size_t gid = (size_t)blockIdx.x * blockDim.x + threadIdx.x;
        int which = gid >= WGROUPS;
        size_t idx = which ? gid - WGROUPS : gid;
        const float* src = which ? wpj : wfc;
        __half* dp = which ? g_Wpj : g_Wfc;
        const float4* s4 = (const float4*)(src + idx * 16);
        uint32_t u[8];
        pack16(s4[0], s4[1], s4[2], s4[3], u);
        uint4* dst = (uint4*)(dp + idx * 16);
        dst[0] = make_uint4(u[0], u[1], u[2], u[3]);
        dst[1] = make_uint4(u[4], u[5], u[6], u[7]);
        return;
    }

    int t = blockIdx.x;
    int warp = threadIdx.x >> 5, lane = threadIdx.x & 31;
    const float4* x4 = (const float4*)(x + (size_t)t * DD);
    const float4* w4 = (const float4*)(rw + (size_t)warp * DD);
    float s = 0.0f;
    #pragma unroll
    for (int i = lane; i < DD / 4; i += 32) {
        float4 a = x4[i], b = w4[i];
        s += a.x * b.x + a.y * b.y + a.z * b.z + a.w * b.w;
    }
    #pragma unroll
    for (int o = 16; o; o >>= 1) s += __shfl_xor_sync(0xffffffffu, s, o);

    __shared__ float lg[NE];
    if (lane == 0) { lg[warp] = s; logits_out[(size_t)t * NE + warp] = s; }
    __syncthreads();
    if (threadIdx.x == 0) {
        int i0 = 0; float v0 = lg[0];
        #pragma unroll
        for (int e = 1; e < NE; e++) if (lg[e] > v0) { v0 = lg[e]; i0 = e; }
        int i1 = -1; float v1 = -3.4e38f;
        #pragma unroll
        for (int e = 0; e < NE; e++) {
            if (e == i0) continue;
            if (lg[e] > v1) { v1 = lg[e]; i1 = e; }
        }
        float e1 = expf(v1 - v0);
        float inv = 1.0f / (1.0f + e1);
        int pos = atomicAdd(&g_count[i0], 1);
        g_tokens[i0][pos] = t; g_gates[i0][pos] = inv;      g_slot[i0][pos] = 0;
        pos = atomicAdd(&g_count[i1], 1);
        g_tokens[i1][pos] = t; g_gates[i1][pos] = e1 * inv; g_slot[i1][pos] = 1;
    }
}

__global__ void k_offsets() {
    if (threadIdx.x == 0) {
        int o = 0;
        for (int e = 0; e < NE; e++) { g_offset[e] = o; o += g_count[e]; }
    }
}

// gather tokens into expert-ordered fp16 rows, pair-permuted. 64 thr/row.
__global__ void k_gather(const float* __restrict__ x) {
    int r = blockIdx.x;
    int e = 0;
    #pragma unroll
    for (int i = 1; i < NE; i++) if (r >= g_offset[i]) e = i;
    int tok = g_tokens[e][r - g_offset[e]];
    int g = threadIdx.x;
    const float4* src = (const float4*)(x + (size_t)tok * DD + g * 16);
    uint32_t u[8];
    pack16(src[0], src[1], src[2], src[3], u);
    uint4* dst = (uint4*)(g_X + (size_t)r * DD + g * 16);
    dst[0] = make_uint4(u[0], u[1], u[2], u[3]);
    dst[1] = make_uint4(u[4], u[5], u[6], u[7]);
}

#define PITCH 160
#define ASTG (128 * PITCH)   // 20480
#define BSTG (256 * PITCH)   // 40960
#define STG  (ASTG + BSTG)

// ---------------- GEMM1 (R13-proven): X @ Wfc^T -> gelu -> H ----------------
// CTA tile 128x256, 512 threads, 16 warps, warp tile 64x32 (2M x 8N grid).
// 3 stages, fill-ahead 1, ONE barrier per chunk, 160B pitch (conflict-free).
__global__ void __launch_bounds__(512, 1) k_gemm1(const float* __restrict__ bias) {
    const int e = blockIdx.z;
    const int count = g_count[e];
    const int mBase = blockIdx.y * 128;
    if (mBase >= count) return;
    const int nBase = blockIdx.x * 256;

    extern __shared__ char smem[];
    const uint32_t sb = smem_u32(smem);
    const int tid = threadIdx.x, wid = tid >> 5, lane = tid & 31;
    const int wm = wid & 1, wn = wid >> 1;          // 2 M-warps x 8 N-warps
    const int t = lane & 3, qr = lane >> 2;

    const __half* Abase = g_X + (size_t)g_offset[e] * DD;
    const __half* Wbase = g_Wfc + (size_t)e * FF * DD + (size_t)nBase * DD;

    auto fill = [&](int c) {
        int s = c % 3;
        uint32_t sa = sb + s * STG;
        uint32_t sbB = sa + ASTG;
        const __half* ac = Abase + c * 64;
        const __half* wc = Wbase + c * 64;
        #pragma unroll
        for (int i = 0; i < 2; i++) {                 // A: 128 rows x 8 segs(16B)
            int o = tid + i * 512; int r = o >> 3, sg = o & 7;
            int rr = mBase + r; if (rr >= count) rr = count - 1;
            cp16(sa + r * PITCH + sg * 16, ac + (size_t)rr * DD + sg * 8);
        }
        #pragma unroll
        for (int i = 0; i < 4; i++) {                 // B: 256 rows x 8 segs
            int o = tid + i * 512; int r = o >> 3, sg = o & 7;
            cp16(sbB + r * PITCH + sg * 16, wc + (size_t)r * DD + sg * 8);
        }
        cp_commit();
    };

    float acc[4][4][4];
    #pragma unroll
    for (int a = 0; a < 4; a++)
        #pragma unroll
        for (int b = 0; b < 4; b++)
            #pragma unroll
            for (int c = 0; c < 4; c++) acc[a][b][c] = 0.0f;

    constexpr int NC = DD / 64;   // 16
    fill(0);

    for (int c = 0; c < NC; c++) {
        if (c + 1 < NC) { fill(c + 1); cp_wait<1>(); }
        else            { cp_wait<0>(); }
        __syncthreads();

        const char* sa  = smem + (c % 3) * STG;
        const char* sbp = sa + ASTG;

        #pragma unroll
        for (int kk = 0; kk < 4; kk++) {
            uint2 af[4][2], bf[4];
            #pragma unroll
            for (int mi = 0; mi < 4; mi++) {
                int r0 = wm * 64 + mi * 16 + qr;
                af[mi][0] = *(const uint2*)(sa + r0 * PITCH + kk * 32 + t * 8);
                af[mi][1] = *(const uint2*)(sa + (r0 + 8) * PITCH + kk * 32 + t * 8);
            }
            #pragma unroll
            for (int ni = 0; ni < 4; ni++) {
                int c0 = wn * 32 + ni * 8 + qr;
                bf[ni] = *(const uint2*)(sbp + c0 * PITCH + kk * 32 + t * 8);
            }
            #pragma unroll
            for (int mi = 0; mi < 4; mi++)
                #pragma unroll
                for (int ni = 0; ni < 4; ni++)
                    mma_f16(acc[mi][ni],
                            af[mi][0].x, af[mi][1].x,
                            af[mi][0].y, af[mi][1].y,
                            bf[ni].x,    bf[ni].y);
        }
    }

    // epilogue: gelu(+bfc) -> g_H (fp16, permuted)
    #pragma unroll
    for (int mi = 0; mi < 4; mi++) {
        #pragma unroll
        for (int half = 0; half < 2; half++) {
            int rloc = wm * 64 + mi * 16 + qr + half * 8;
            int gr = mBase + rloc;
            if (gr >= count) continue;
            __half* hrow = g_H + (size_t)(g_offset[e] + gr) * FF;
            #pragma unroll
            for (int ni = 0; ni < 4; ni++) {
                int blk = nBase + wn * 32 + ni * 8;
                float b0 = bias[(size_t)e * FF + blk + 2 * t];
                float b1 = bias[(size_t)e * FF + blk + 2 * t + 1];
                float a0 = acc[mi][ni][half * 2 + 0] + b0;
                float a1 = acc[mi][ni][half * 2 + 1] + b1;
                float g0 = 0.5f * a0 * (1.0f + erff(a0 * 0.70710678118654752f));
                float g1 = 0.5f * a1 * (1.0f + erff(a1 * 0.70710678118654752f));
                int group = (blk >> 4) << 4;
                int off = (2 * t + (ni & 1)) * 2;
                __half2 hv = __floats2half2_rn(g0, g1);
                *(uint32_t*)(hrow + group + off) = *(uint32_t*)&hv;
            }
        }
    }
}

// ---------------- GEMM2: H @ Wpj^T -> gate*(.+bproj) -> g_part ----------------
// CTA tile 64(M) x 256(N), 256 threads, 8 warps, warp tile 32x64 (2M x 4N grid).
// Finer M-tiles quadruple real-CTA count (~2048) to kill the 1.7-wave tail.
// 3 stages, fill-ahead 1, one barrier per chunk, 160B pitch.
#define A2STG (64 * PITCH)            // 10240
#define STG2  (A2STG + BSTG)          // 51200

__global__ void __launch_bounds__(256, 1) k_gemm2(const float* __restrict__ bias) {
    const int e = blockIdx.z;
    const int count = g_count[e];
    const int mBase = blockIdx.y * 64;
    if (mBase >= count) return;
    const int nBase = blockIdx.x * 256;

    extern __shared__ char smem[];
    const uint32_t sb = smem_u32(smem);
    const int tid = threadIdx.x, wid = tid >> 5, lane = tid & 31;
    const int wm = wid & 1, wn = wid >> 1;          // 2 M-warps x 4 N-warps
    const int t = lane & 3, qr = lane >> 2;

    const __half* Abase = g_H + (size_t)g_offset[e] * FF;
    const __half* Wbase = g_Wpj + (size_t)e * DD * FF + (size_t)nBase * FF;

    auto fill = [&](int c) {
        int s = c % 3;
        uint32_t sa = sb + s * STG2;
        uint32_t sbB = sa + A2STG;
        const __half* ac = Abase + c * 64;
        const __half* wc = Wbase + c * 64;
        #pragma unroll
        for (int i = 0; i < 2; i++) {                 // A: 64 rows x 8 segs(16B)
            int o = tid + i * 256; int r = o >> 3, sg = o & 7;
            int rr = mBase + r; if (rr >= count) rr = count - 1;
            cp16(sa + r * PITCH + sg * 16, ac + (size_t)rr * FF + sg * 8);
        }
        #pragma unroll
        for (int i = 0; i < 8; i++) {                 // B: 256 rows x 8 segs
            int o = tid + i * 256; int r = o >> 3, sg = o & 7;
            cp16(sbB + r * PITCH + sg * 16, wc + (size_t)r * FF + sg * 8);
        }
        cp_commit();
    };

    float acc[2][8][4];
    #pragma unroll
    for (int a = 0; a < 2; a++)
        #pragma unroll
        for (int b = 0; b < 8; b++)
            #pragma unroll
            for (int c = 0; c < 4; c++) acc[a][b][c] = 0.0f;

    constexpr int NC = FF / 64;   // 64
    fill(0);

    for (int c = 0; c < NC; c++) {
        if (c + 1 < NC) { fill(c + 1); cp_wait<1>(); }
        else            { cp_wait<0>(); }
        __syncthreads();

        const char* sa  = smem + (c % 3) * STG2;
        const char* sbp = sa + A2STG;

        #pragma unroll
        for (int kk = 0; kk < 4; kk++) {
            uint2 af[2][2], bf[8];
            #pragma unroll
            for (int mi = 0; mi < 2; mi++) {
                int r0 = wm * 32 + mi * 16 + qr;
                af[mi][0] = *(const uint2*)(sa + r0 * PITCH + kk * 32 + t * 8);
                af[mi][1] = *(const uint2*)(sa + (r0 + 8) * PITCH + kk * 32 + t * 8);
            }
            #pragma unroll
            for (int ni = 0; ni < 8; ni++) {
                int c0 = wn * 64 + ni * 8 + qr;
                bf[ni] = *(const uint2*)(sbp + c0 * PITCH + kk * 32 + t * 8);
            }
            #pragma unroll
            for (int mi = 0; mi < 2; mi++)
                #pragma unroll
                for (int ni = 0; ni < 8; ni++)
                    mma_f16(acc[mi][ni],
                            af[mi][0].x, af[mi][1].x,
                            af[mi][0].y, af[mi][1].y,
                            bf[ni].x,    bf[ni].y);
        }
    }

    #pragma unroll
    for (int mi = 0; mi < 2; mi++) {
        #pragma unroll
        for (int half = 0; half < 2; half++) {
            int rloc = wm * 32 + mi * 16 + qr + half * 8;
            int gr = mBase + rloc;
            if (gr >= count) continue;
            int tok = g_tokens[e][gr];
            float gate = g_gates[e][gr];
            int slot = g_slot[e][gr];
            float* dst = g_part[slot] + (size_t)tok * DD;
            #pragma unroll
            for (int ni = 0; ni < 8; ni++) {
                int blk = nBase + wn * 64 + ni * 8;
                float2 bb = *(const float2*)(bias + (size_t)e * DD + blk + 2 * t);
                float2 v;
                v.x = gate * (acc[mi][ni][half * 2 + 0] + bb.x);
                v.y = gate * (acc[mi][ni][half * 2 + 1] + bb.y);
                *(float2*)(dst + blk + 2 * t) = v;
            }
        }
    }
}

// ---------------- LayerNorm ----------------
__global__ void k_ln(const float* __restrict__ gamma, const float* __restrict__ beta,
                     float* __restrict__ out) {
    int t = blockIdx.x;
    __shared__ float row[DD];
    __shared__ float red[32];
    const float* p0 = g_part[0] + (size_t)t * DD;
    const float* p1 = g_part[1] + (size_t)t * DD;
    float s = 0.0f;
    for (int i = threadIdx.x; i < DD; i += 256) {
        float v = p0[i] + p1[i];
        row[i] = v; s += v;
    }
    s = blockReduceSum(s, red);
    float mu = s * (1.0f / DD);
    float s2 = 0.0f;
    for (int i = threadIdx.x; i < DD; i += 256) {
        float d = row[i] - mu; s2 += d * d;
    }
    s2 = blockReduceSum(s2, red);
    float rstd = rsqrtf(s2 * (1.0f / DD) + 1e-5f);
    for (int i = threadIdx.x; i < DD; i += 256)
        out[(size_t)t * DD + i] = (row[i] - mu) * rstd * gamma[i] + beta[i];
}

// ---------------- launch ----------------
extern "C" void kernel_launch(void* const* d_in, const int* in_sizes, int n_in,
                              void* d_out, int out_size) {
    (void)in_sizes; (void)n_in; (void)out_size;
    const float* x   = (const float*)d_in[0];
    const float* rw  = (const float*)d_in[1];
    const float* wfc = (const float*)d_in[2];
    const float* bfc = (const float*)d_in[3];
    const float* wpj = (const float*)d_in[4];
    const float* bpj = (const float*)d_in[5];
    const float* lg  = (const float*)d_in[6];
    const float* lb  = (const float*)d_in[7];

    float* out    = (float*)d_out;
    float* logits = out + (size_t)NT * DD;

    const int SMEM1 = 3 * STG;    // 184320
    const int SMEM2 = 3 * STG2;   // 153600
    cudaFuncSetAttribute((const void*)k_gemm1,
                         cudaFuncAttributeMaxDynamicSharedMemorySize, SMEM1);
    cudaFuncSetAttribute((const void*)k_gemm2,
                         cudaFuncAttributeMaxDynamicSharedMemorySize, SMEM2);

    k_zero<<<1, 32>>>();
    k_router<<<dim3(NT, 2), 256>>>(x, rw, logits, wfc, wpj);
    k_offsets<<<1, 1>>>();
    k_gather<<<NROWS, 64>>>(x);
    k_gemm1<<<dim3(FF / 256, NT / 128, NE), 512, SMEM1>>>(bfc);
    k_gemm2<<<dim3(DD / 256, NT / 64, NE), 256, SMEM2>>>(bpj);
    k_ln<<<NT, 256>>>(lg, lb, out);
}

// round 16
// speedup vs baseline: 1.1025x; 1.1025x over previous
#include <cuda_runtime.h>
#include <cuda_fp16.h>
#include <math.h>
#include <stdint.h>

#define NT 16384    // tokens = B*T
#define DD 1024     // hidden
#define FF 4096     // ffn
#define NE 8        // experts
#define NROWS 32768 // 2*NT expert-row slots
#define WGROUPS 2097152  // NE*FF*DD/16 groups per weight tensor

// ---------------- device scratch (static, allocation-free) ----------------
__device__ int    g_count[NE];
__device__ int    g_offset[NE];
__device__ int    g_tokens[NE][NT];
__device__ float  g_gates[NE][NT];
__device__ int    g_slot[NE][NT];
__device__ __half g_X[(size_t)NROWS * DD];      // gathered, fp16, pair-permuted
__device__ __half g_H[(size_t)NROWS * FF];      // gelu(fc), fp16, pair-permuted
__device__ float  g_part[2][(size_t)NT * DD];   // per-slot partial outputs (fp32)
__device__ __half g_Wfc[(size_t)NE * FF * DD];  // fp16 + permuted weights
__device__ __half g_Wpj[(size_t)NE * DD * FF];

// ---------------- helpers ----------------
__device__ __forceinline__ void cp16(uint32_t d, const void* s) {
    asm volatile("cp.async.cg.shared.global [%0], [%1], 16;" :: "r"(d), "l"(s));
}
__device__ __forceinline__ void cp_commit() { asm volatile("cp.async.commit_group;"); }
template<int N> __device__ __forceinline__ void cp_wait() {
    asm volatile("cp.async.wait_group %0;" :: "n"(N));
}
__device__ __forceinline__ uint32_t smem_u32(const void* p) {
    uint32_t a;
    asm("{ .reg .u64 t; cvta.to.shared.u64 t, %1; cvt.u32.u64 %0, t; }" : "=r"(a) : "l"(p));
    return a;
}
// fp16 MMA m16n8k16, fp32 accumulate
__device__ __forceinline__ void mma_f16(float c[4], uint32_t a0, uint32_t a1,
                                        uint32_t a2, uint32_t a3,
                                        uint32_t b0, uint32_t b1) {
    asm volatile(
        "mma.sync.aligned.m16n8k16.row.col.f32.f16.f16.f32 "
        "{%0,%1,%2,%3}, {%4,%5,%6,%7}, {%8,%9}, {%0,%1,%2,%3};"
        : "+f"(c[0]), "+f"(c[1]), "+f"(c[2]), "+f"(c[3])
        : "r"(a0), "r"(a1), "r"(a2), "r"(a3), "r"(b0), "r"(b1));
}
__device__ __forceinline__ float blockReduceSum(float v, float* red) {
    __syncthreads();
    int lane = threadIdx.x & 31, warp = threadIdx.x >> 5;
    #pragma unroll
    for (int o = 16; o; o >>= 1) v += __shfl_xor_sync(0xffffffffu, v, o);
    if (lane == 0) red[warp] = v;
    __syncthreads();
    if (warp == 0) {
        float s = (lane < 8) ? red[lane] : 0.0f;
        #pragma unroll
        for (int o = 4; o; o >>= 1) s += __shfl_xor_sync(0xffffffffu, s, o);
        if (lane == 0) red[0] = s;
    }
    __syncthreads();
    return red[0];
}

// pack 16 floats -> 16 permuted fp16 (pair order [0,4,1,5,2,6,3,7]) as 8 u32
__device__ __forceinline__ void pack16(const float4 f0, const float4 f1,
                                       const float4 f2, const float4 f3,
                                       uint32_t u[8]) {
    __half2 p[8];
    p[0] = __floats2half2_rn(f0.x, f0.y); p[1] = __floats2half2_rn(f0.z, f0.w);
    p[2] = __floats2half2_rn(f1.x, f1.y); p[3] = __floats2half2_rn(f1.z, f1.w);
    p[4] = __floats2half2_rn(f2.x, f2.y); p[5] = __floats2half2_rn(f2.z, f2.w);
    p[6] = __floats2half2_rn(f3.x, f3.y); p[7] = __floats2half2_rn(f3.z, f3.w);
    u[0] = *(uint32_t*)&p[0]; u[1] = *(uint32_t*)&p[4];
    u[2] = *(uint32_t*)&p[1]; u[3] = *(uint32_t*)&p[5];
    u[4] = *(uint32_t*)&p[2]; u[5] = *(uint32_t*)&p[6];
    u[6] = *(uint32_t*)&p[3]; u[7] = *(uint32_t*)&p[7];
}

// ---------------- small kernels ----------------
__global__ void k_zero() { if (threadIdx.x < NE) g_count[threadIdx.x] = 0; }

// grid (NT, 2): y=0 -> router blocks (unchanged R13 router);
//               y=1 -> pure weight-conversion blocks (R13 k_round, co-scheduled).
__global__ void k_router(const float* __restrict__ x, const float* __restrict__ rw,
                         float* __restrict__ logits_out,
                         const float* __restrict__ wfc, const float* __restrict__ wpj) {
    if (blockIdx.y == 1) {
        size_t gid = (size_t)blockIdx.x * blockDim.x + threadIdx.x;  // 16384*256 slots
        int which = gid >= WGROUPS;
        size_t idx = which ? gid - WGROUPS : gid;
        const float* src = which ? wpj : wfc;
        __half* dp = which ? g_Wpj : g_Wfc;
        const float4* s4 = (const float4*)(src + idx * 16);
        uint32_t u[8];
        pack16(s4[0], s4[1], s4[2], s4[3], u);
        uint4* dst = (uint4*)(dp + idx * 16);
        dst[0] = make_uint4(u[0], u[1], u[2], u[3]);
        dst[1] = make_uint4(u[4], u[5], u[6], u[7]);
        return;
    }

    int t = blockIdx.x;
    int warp = threadIdx.x >> 5, lane = threadIdx.x & 31;
    const float4* x4 = (const float4*)(x + (size_t)t * DD);
    const float4* w4 = (const float4*)(rw + (size_t)warp * DD);
    float s = 0.0f;
    #pragma unroll
    for (int i = lane; i < DD / 4; i += 32) {
        float4 a = x4[i], b = w4[i];
        s += a.x * b.x + a.y * b.y + a.z * b.z + a.w * b.w;
    }
    #pragma unroll
    for (int o = 16; o; o >>= 1) s += __shfl_xor_sync(0xffffffffu, s, o);

    __shared__ float lg[NE];
    if (lane == 0) { lg[warp] = s; logits_out[(size_t)t * NE + warp] = s; }
    __syncthreads();
    if (threadIdx.x == 0) {
        int i0 = 0; float v0 = lg[0];
        #pragma unroll
        for (int e = 1; e < NE; e++) if (lg[e] > v0) { v0 = lg[e]; i0 = e; }
        int i1 = -1; float v1 = -3.4e38f;
        #pragma unroll
        for (int e = 0; e < NE; e++) {
            if (e == i0) continue;
            if (lg[e] > v1) { v1 = lg[e]; i1 = e; }
        }
        float e1 = expf(v1 - v0);
        float inv = 1.0f / (1.0f + e1);
        int pos = atomicAdd(&g_count[i0], 1);
        g_tokens[i0][pos] = t; g_gates[i0][pos] = inv;      g_slot[i0][pos] = 0;
        pos = atomicAdd(&g_count[i1], 1);
        g_tokens[i1][pos] = t; g_gates[i1][pos] = e1 * inv; g_slot[i1][pos] = 1;
    }
}

__global__ void k_offsets() {
    if (threadIdx.x == 0) {
        int o = 0;
        for (int e = 0; e < NE; e++) { g_offset[e] = o; o += g_count[e]; }
    }
}

// gather tokens into expert-ordered fp16 rows, pair-permuted. 64 thr/row.
__global__ void k_gather(const float* __restrict__ x) {
    int r = blockIdx.x;
    int e = 0;
    #pragma unroll
    for (int i = 1; i < NE; i++) if (r >= g_offset[i]) e = i;
    int tok = g_tokens[e][r - g_offset[e]];
    int g = threadIdx.x;
    const float4* src = (const float4*)(x + (size_t)tok * DD + g * 16);
    uint32_t u[8];
    pack16(src[0], src[1], src[2], src[3], u);
    uint4* dst = (uint4*)(g_X + (size_t)r * DD + g * 16);
    dst[0] = make_uint4(u[0], u[1], u[2], u[3]);
    dst[1] = make_uint4(u[4], u[5], u[6], u[7]);
}

// ---------------- pipelined fp16 mma.sync grouped GEMM (R13-proven) ----------------
// CTA tile 128(M) x 256(N), 512 threads, 16 warps, warp tile 64x32 (2M x 8N grid).
// K-chunk = 64 halfs. SMEM row pitch = 160B (128B data + 32B pad): conflict-free.
// 3 stages, fill-ahead 1, ONE __syncthreads per chunk.
// MODE 0: A=g_X -> epilogue gelu(+bfc) -> g_H (fp16, permuted)
// MODE 1: A=g_H -> epilogue gate*( . + bproj) -> g_part[slot] (fp32)
#define PITCH 160
#define ASTG (128 * PITCH)   // 20480
#define BSTG (256 * PITCH)   // 40960
#define STG  (ASTG + BSTG)

template<int K, int NTOT, int MODE>
__global__ void __launch_bounds__(512, 1) k_gemm(const float* __restrict__ bias) {
    const int e = blockIdx.z;
    const int count = g_count[e];
    const int mBase = blockIdx.y * 128;
    if (mBase >= count) return;
    const int nBase = blockIdx.x * 256;

    extern __shared__ char smem[];
    const uint32_t sb = smem_u32(smem);
    const int tid = threadIdx.x, wid = tid >> 5, lane = tid & 31;
    const int wm = wid & 1, wn = wid >> 1;          // 2 M-warps x 8 N-warps
    const int t = lane & 3, qr = lane >> 2;

    const __half* Abase = (MODE ? g_H : g_X) + (size_t)g_offset[e] * K;
    const __half* Wbase = (MODE ? g_Wpj : g_Wfc) + (size_t)e * NTOT * K + (size_t)nBase * K;

    auto fill = [&](int c) {
        int s = c % 3;
        uint32_t sa = sb + s * STG;
        uint32_t sbB = sa + ASTG;
        const __half* ac = Abase + c * 64;
        const __half* wc = Wbase + c * 64;
        #pragma unroll
        for (int i = 0; i < 2; i++) {                 // A: 128 rows x 8 segs(16B)
            int o = tid + i * 512; int r = o >> 3, sg = o & 7;
            int rr = mBase + r; if (rr >= count) rr = count - 1;
            cp16(sa + r * PITCH + sg * 16, ac + (size_t)rr * K + sg * 8);
        }
        #pragma unroll
        for (int i = 0; i < 4; i++) {                 // B: 256 rows x 8 segs
            int o = tid + i * 512; int r = o >> 3, sg = o & 7;
            cp16(sbB + r * PITCH + sg * 16, wc + (size_t)r * K + sg * 8);
        }
        cp_commit();
    };

    float acc[4][4][4];
    #pragma unroll
    for (int a = 0; a < 4; a++)
        #pragma unroll
        for (int b = 0; b < 4; b++)
            #pragma unroll
            for (int c = 0; c < 4; c++) acc[a][b][c] = 0.0f;

    constexpr int NC = K / 64;
    fill(0);

    for (int c = 0; c < NC; c++) {
        if (c + 1 < NC) { fill(c + 1); cp_wait<1>(); }
        else            { cp_wait<0>(); }
        __syncthreads();

        const char* sa  = smem + (c % 3) * STG;
        const char* sbp = sa + ASTG;

        #pragma unroll
        for (int kk = 0; kk < 4; kk++) {
            uint2 af[4][2], bf[4];
            #pragma unroll
            for (int mi = 0; mi < 4; mi++) {
                int r0 = wm * 64 + mi * 16 + qr;
                af[mi][0] = *(const uint2*)(sa + r0 * PITCH + kk * 32 + t * 8);
                af[mi][1] = *(const uint2*)(sa + (r0 + 8) * PITCH + kk * 32 + t * 8);
            }
            #pragma unroll
            for (int ni = 0; ni < 4; ni++) {
                int c0 = wn * 32 + ni * 8 + qr;
                bf[ni] = *(const uint2*)(sbp + c0 * PITCH + kk * 32 + t * 8);
            }
            #pragma unroll
            for (int mi = 0; mi < 4; mi++)
                #pragma unroll
                for (int ni = 0; ni < 4; ni++)
                    mma_f16(acc[mi][ni],
                            af[mi][0].x, af[mi][1].x,
                            af[mi][0].y, af[mi][1].y,
                            bf[ni].x,    bf[ni].y);
        }
    }

    // ---------------- epilogue ----------------
    #pragma unroll
    for (int mi = 0; mi < 4; mi++) {
        #pragma unroll
        for (int half = 0; half < 2; half++) {
            int rloc = wm * 64 + mi * 16 + qr + half * 8;
            int gr = mBase + rloc;
            if (gr >= count) continue;
            if (MODE == 0) {
                __half* hrow = g_H + (size_t)(g_offset[e] + gr) * FF;
                #pragma unroll
                for (int ni = 0; ni < 4; ni++) {
                    int blk = nBase + wn * 32 + ni * 8;
                    float b0 = bias[(size_t)e * NTOT + blk + 2 * t];
                    float b1 = bias[(size_t)e * NTOT + blk + 2 * t + 1];
                    float a0 = acc[mi][ni][half * 2 + 0] + b0;
                    float a1 = acc[mi][ni][half * 2 + 1] + b1;
                    float g0 = 0.5f * a0 * (1.0f + erff(a0 * 0.70710678118654752f));
                    float g1 = 0.5f * a1 * (1.0f + erff(a1 * 0.70710678118654752f));
                    int group = (blk >> 4) << 4;
                    int off = (2 * t + (ni & 1)) * 2;
                    __half2 hv = __floats2half2_rn(g0, g1);
                    *(uint32_t*)(hrow + group + off) = *(uint32_t*)&hv;
                }
            } else {
                int tok = g_tokens[e][gr];
                float gate = g_gates[e][gr];
                int slot = g_slot[e][gr];
                float* dst = g_part[slot] + (size_t)tok * DD;
                #pragma unroll
                for (int ni = 0; ni < 4; ni++) {
                    int blk = nBase + wn * 32 + ni * 8;
                    float2 bb = *(const float2*)(bias + (size_t)e * NTOT + blk + 2 * t);
                    float2 v;
                    v.x = gate * (acc[mi][ni][half * 2 + 0] + bb.x);
                    v.y = gate * (acc[mi][ni][half * 2 + 1] + bb.y);
                    *(float2*)(dst + blk + 2 * t) = v;
                }
            }
        }
    }
}

// ---------------- LayerNorm ----------------
__global__ void k_ln(const float* __restrict__ gamma, const float* __restrict__ beta,
                     float* __restrict__ out) {
    int t = blockIdx.x;
    __shared__ float row[DD];
    __shared__ float red[32];
    const float* p0 = g_part[0] + (size_t)t * DD;
    const float* p1 = g_part[1] + (size_t)t * DD;
    float s = 0.0f;
    for (int i = threadIdx.x; i < DD; i += 256) {
        float v = p0[i] + p1[i];
        row[i] = v; s += v;
    }
    s = blockReduceSum(s, red);
    float mu = s * (1.0f / DD);
    float s2 = 0.0f;
    for (int i = threadIdx.x; i < DD; i += 256) {
        float d = row[i] - mu; s2 += d * d;
    }
    s2 = blockReduceSum(s2, red);
    float rstd = rsqrtf(s2 * (1.0f / DD) + 1e-5f);
    for (int i = threadIdx.x; i < DD; i += 256)
        out[(size_t)t * DD + i] = (row[i] - mu) * rstd * gamma[i] + beta[i];
}

// ---------------- launch ----------------
extern "C" void kernel_launch(void* const* d_in, const int* in_sizes, int n_in,
                              void* d_out, int out_size) {
    (void)in_sizes; (void)n_in; (void)out_size;
    const float* x   = (const float*)d_in[0];
    const float* rw  = (const float*)d_in[1];
    const float* wfc = (const float*)d_in[2];
    const float* bfc = (const float*)d_in[3];
    const float* wpj = (const float*)d_in[4];
    const float* bpj = (const float*)d_in[5];
    const float* lg  = (const float*)d_in[6];
    const float* lb  = (const float*)d_in[7];

    float* out    = (float*)d_out;
    float* logits = out + (size_t)NT * DD;

    const int SMEM_SZ = 3 * STG;   // 184320 B per CTA
    cudaFuncSetAttribute((const void*)k_gemm<DD, FF, 0>,
                         cudaFuncAttributeMaxDynamicSharedMemorySize, SMEM_SZ);
    cudaFuncSetAttribute((const void*)k_gemm<FF, DD, 1>,
                         cudaFuncAttributeMaxDynamicSharedMemorySize, SMEM_SZ);

    k_zero<<<1, 32>>>();
    k_router<<<dim3(NT, 2), 256>>>(x, rw, logits, wfc, wpj);
    k_offsets<<<1, 1>>>();
    k_gather<<<NROWS, 64>>>(x);
    k_gemm<DD, FF, 0><<<dim3(FF / 256, NT / 128, NE), 512, SMEM_SZ>>>(bfc);
    k_gemm<FF, DD, 1><<<dim3(DD / 256, NT / 128, NE), 512, SMEM_SZ>>>(bpj);
    k_ln<<<NT, 256>>>(lg, lb, out);
}